// round 17
// baseline (speedup 1.0000x reference)
#include <cuda_runtime.h>
#include <cuda_bf16.h>

// Problem constants (match reference)
#define B_  32
#define S_  128
#define I_  64
#define H_  1024
#define T_  4          // NUM_TIME_STEPS
#define DECAY      0.9f
#define THRESHOLD  1.0f
#define BETA       5.0f

// Balanced chunked scan, NCHUNK=8, WARMUP_S=18 (identical to the 182.4us
// best: rel_err 3.36e-4, 3x under the bar — do not change the math).
//   chunk 0:   owns s [0,30)                 warm-up: none (EXACT)
//   chunk c>0: owns s [30+14(c-1), 30+14c)   warm-up: 18 s-steps
// Chunks 0..6 need drive s < 114; only chunk 7 needs s in [96,128).
#define NCHUNK    8
#define WARMUP_S  18
#define OWN0      30

// Overlap split: K1a produces s [0,114) (89% of K1), then K2a (chunks 0-6)
// forks onto a side stream and overlaps K1b (s [114,128)). Only K2b
// (chunk 7, 128 blocks) is exposed at the end.
#define S_SPLIT   114

// 16 MB scratch for drive[b,s,h] (device global: no allocation, graph-safe)
__device__ float g_drive[(size_t)B_ * S_ * H_];

// ---------------------------------------------------------------------------
// Streams/events: created once at static-init (no device-memory allocation).
// Fallback to serial default-stream execution if creation fails.
// ---------------------------------------------------------------------------
static cudaStream_t g_s1 = 0;
static cudaEvent_t  g_evA = 0, g_evB = 0;
static bool         g_pipe_ok = false;

static bool init_pipe()
{
    if (cudaStreamCreateWithFlags(&g_s1, cudaStreamNonBlocking) != cudaSuccess) return false;
    if (cudaEventCreateWithFlags(&g_evA, cudaEventDisableTiming) != cudaSuccess) return false;
    if (cudaEventCreateWithFlags(&g_evB, cudaEventDisableTiming) != cudaSuccess) return false;
    return true;
}
static bool g_pipe_init = (g_pipe_ok = init_pipe());

// ---------------------------------------------------------------------------
// Kernel 1: drive[b,s,h] = sum_i enc[i,h] * x[b,s,i,h] for s in [s0, s0+slen).
// One block per (b,s) pair; inner loop identical to the proven 86%-of-spec
// version. Block->(b,s) mapping order is irrelevant for a streaming kernel.
// ---------------------------------------------------------------------------
#define K1_TPB 256

__global__ __launch_bounds__(K1_TPB)
void drive_kernel(const float* __restrict__ x,
                  const float* __restrict__ enc,
                  float* __restrict__ drive,
                  int s0, int slen)
{
    const int bid = blockIdx.x;
    const int s   = s0 + (bid % slen);
    const int b   = bid / slen;
    const int bs  = b * S_ + s;
    const int h4  = threadIdx.x;                        // float4 column 0..255

    const float4* xp = reinterpret_cast<const float4*>(x + (size_t)bs * I_ * H_) + h4;
    const float4* ep = reinterpret_cast<const float4*>(enc) + h4;

    float4 a0 = make_float4(0.f, 0.f, 0.f, 0.f);
    float4 a1 = make_float4(0.f, 0.f, 0.f, 0.f);

#pragma unroll
    for (int i = 0; i < I_; i += 2) {
        const float4 xv0 = __ldcs(&xp[(i + 0) * (H_ / 4)]);
        const float4 xv1 = __ldcs(&xp[(i + 1) * (H_ / 4)]);
        const float4 ev0 = __ldg (&ep[(i + 0) * (H_ / 4)]);
        const float4 ev1 = __ldg (&ep[(i + 1) * (H_ / 4)]);
        a0.x = fmaf(ev0.x, xv0.x, a0.x);
        a0.y = fmaf(ev0.y, xv0.y, a0.y);
        a0.z = fmaf(ev0.z, xv0.z, a0.z);
        a0.w = fmaf(ev0.w, xv0.w, a0.w);
        a1.x = fmaf(ev1.x, xv1.x, a1.x);
        a1.y = fmaf(ev1.y, xv1.y, a1.y);
        a1.z = fmaf(ev1.z, xv1.z, a1.z);
        a1.w = fmaf(ev1.w, xv1.w, a1.w);
    }

    float4 r;
    r.x = a0.x + a1.x;
    r.y = a0.y + a1.y;
    r.z = a0.z + a1.z;
    r.w = a0.w + a1.w;
    reinterpret_cast<float4*>(drive)[(size_t)bs * (H_ / 4) + h4] = r;
}

// ---------------------------------------------------------------------------
// Kernel 2: balanced chunked LIF scan over chunks [chunk_base, chunk_base+n).
// Body identical to the proven best (split loops, tanh.approx, scalar lanes).
// ---------------------------------------------------------------------------
#define K2_TPB 256

__device__ __forceinline__ float tanh_approx(float z)
{
    float r;
    asm("tanh.approx.f32 %0, %1;" : "=f"(r) : "f"(z));
    return r;
}

__device__ __forceinline__ void lif_substep(float& v, float d, float& spike)
{
    v = fmaf(DECAY, v, d);
    const float z = fmaf(0.5f * BETA, v, -0.5f * BETA * THRESHOLD);
    spike = fmaf(0.5f, tanh_approx(z), 0.5f);
    v -= spike * THRESHOLD;
}

__global__ __launch_bounds__(K2_TPB)
void lif_scan_kernel(const float* __restrict__ drive,
                     float* __restrict__ out,
                     int chunk_base)
{
    const int idx   = blockIdx.x * K2_TPB + threadIdx.x;
    const int h     = idx & (H_ - 1);
    const int bc    = idx >> 10;
    const int b     = bc & (B_ - 1);
    const int chunk = chunk_base + (bc >> 5);

    // Balanced ownership: chunk 0 owns OWN0 steps (exact), others 14 each
    // with exactly WARMUP_S warm-up steps. Max lane work: 32 s-steps.
    const int s_own   = (chunk == 0) ? 0 : (OWN0 + 14 * (chunk - 1));
    const int s_end   = (chunk == 0) ? OWN0 : (s_own + 14);
    const int s_start = (chunk == 0) ? 0 : (s_own - WARMUP_S);

    const float* dp = drive + (size_t)b * S_ * H_ + h;
    float*       ob = out   + (size_t)b * S_ * T_ * H_ + h;

    float v = 0.0f;
    float spike;

    // Warm-up: run the recurrence, discard spikes.
    for (int s = s_start; s < s_own; s++) {
        const float d = __ldg(dp + (size_t)s * H_);
#pragma unroll
        for (int t = 0; t < T_; t++)
            lif_substep(v, d, spike);
    }

    // Owned range: store spikes.
    for (int s = s_own; s < s_end; s++) {
        const float d = __ldg(dp + (size_t)s * H_);
        float* os = ob + (size_t)s * T_ * H_;
#pragma unroll
        for (int t = 0; t < T_; t++) {
            lif_substep(v, d, spike);
            __stcs(os + (size_t)t * H_, spike);
        }
    }

    // Last chunk owns the final state.
    if (chunk == NCHUNK - 1)
        out[(size_t)B_ * S_ * T_ * H_ + (size_t)b * H_ + h] = v;
}

// ---------------------------------------------------------------------------
extern "C" void kernel_launch(void* const* d_in, const int* in_sizes, int n_in,
                              void* d_out, int out_size)
{
    const float* x   = (const float*)d_in[0];   // [32,128,64,1024] f32
    const float* enc = (const float*)d_in[1];   // [64,1024] f32
    float* out = (float*)d_out;                 // [32*512*1024 + 32*1024] f32

    float* drive = nullptr;
    cudaGetSymbolAddress((void**)&drive, g_drive);   // host-side, graph-safe

    const int k1a_blocks = B_ * S_SPLIT;          // 3648: s [0,114)
    const int k1b_blocks = B_ * (S_ - S_SPLIT);   // 448:  s [114,128)
    const int k2a_blocks = 7 * B_ * (H_ / K2_TPB);// 896:  chunks 0-6
    const int k2b_blocks = 1 * B_ * (H_ / K2_TPB);// 128:  chunk 7

    if (g_pipe_ok) {
        // main: K1a ---------------------- K1b ---- K2b(chunk7) -- wait(evB)
        //                  \evA-> s1: K2a(chunks 0-6) ------evB/
        drive_kernel<<<k1a_blocks, K1_TPB>>>(x, enc, drive, 0, S_SPLIT);
        cudaEventRecord(g_evA, 0);
        cudaStreamWaitEvent(g_s1, g_evA, 0);
        lif_scan_kernel<<<k2a_blocks, K2_TPB, 0, g_s1>>>(drive, out, 0);
        cudaEventRecord(g_evB, g_s1);

        drive_kernel<<<k1b_blocks, K1_TPB>>>(x, enc, drive, S_SPLIT, S_ - S_SPLIT);
        lif_scan_kernel<<<k2b_blocks, K2_TPB>>>(drive, out, 7);

        cudaStreamWaitEvent(0, g_evB, 0);
    } else {
        // Serial fallback (identical math, no overlap).
        drive_kernel<<<k1a_blocks, K1_TPB>>>(x, enc, drive, 0, S_SPLIT);
        drive_kernel<<<k1b_blocks, K1_TPB>>>(x, enc, drive, S_SPLIT, S_ - S_SPLIT);
        lif_scan_kernel<<<k2a_blocks, K2_TPB>>>(drive, out, 0);
        lif_scan_kernel<<<k2b_blocks, K2_TPB>>>(drive, out, 7);
    }
}